// round 2
// baseline (speedup 1.0000x reference)
#include <cuda_runtime.h>
#include <cstdint>

// out[dst[e]*64 + j] += src_emb[src[e]*64 + j] * att[e]
// D = 64 floats = 16 float4 per edge -> 16 lanes per edge, one float4 each.
// NOTE: indices arrive as int32 (JAX default x64-disabled downcasts jnp.int64).

static constexpr int D = 64;
static constexpr int LANES_PER_EDGE = 16;  // D/4

__global__ __launch_bounds__(256)
void scatter_mul_sum_kernel(const float* __restrict__ src_emb,
                            const float* __restrict__ e_att,
                            const int* __restrict__ src_idx,
                            const int* __restrict__ dst_idx,
                            float* __restrict__ out,
                            int num_edges)
{
    const long long tid = (long long)blockIdx.x * blockDim.x + threadIdx.x;
    const long long edge = tid >> 4;          // tid / 16
    const int lane = (int)(tid & 15);         // float4 slot within the row
    if (edge >= num_edges) return;

    const long long s = (long long)src_idx[edge];
    const long long d = (long long)dst_idx[edge];
    const float att = __ldg(&e_att[edge]);

    const float4 v = *reinterpret_cast<const float4*>(src_emb + s * D + lane * 4);

    float4 m;
    m.x = v.x * att;
    m.y = v.y * att;
    m.z = v.z * att;
    m.w = v.w * att;

    float* dst_ptr = out + d * D + lane * 4;
    // sm_90+: vector fp32 reduction — 1 op instead of 4 scalar atomicAdds.
    asm volatile("red.global.add.v4.f32 [%0], {%1, %2, %3, %4};"
                 :: "l"(dst_ptr), "f"(m.x), "f"(m.y), "f"(m.z), "f"(m.w)
                 : "memory");
}

extern "C" void kernel_launch(void* const* d_in, const int* in_sizes, int n_in,
                              void* d_out, int out_size)
{
    const float* src_emb = (const float*)d_in[0];   // [N_SRC, 64]
    const float* e_att   = (const float*)d_in[1];   // [E, 1]
    const int*   src_idx = (const int*)d_in[2];     // [E] int32
    const int*   dst_idx = (const int*)d_in[3];     // [E] int32
    float* out = (float*)d_out;                     // [N_DST, 64]

    const int E = in_sizes[2];  // element count of src_idx

    // Output is poisoned to 0xAA; we accumulate with atomics, so zero it first.
    cudaMemsetAsync(d_out, 0, (size_t)out_size * sizeof(float), 0);

    const long long total_threads = (long long)E * LANES_PER_EDGE;
    const int block = 256;
    const int grid = (int)((total_threads + block - 1) / block);
    scatter_mul_sum_kernel<<<grid, block>>>(src_emb, e_att, src_idx, dst_idx, out, E);
}

// round 3
// speedup vs baseline: 1.1382x; 1.1382x over previous
#include <cuda_runtime.h>
#include <cstdint>

// out[dst[e]*64 + j] += src_emb[src[e]*64 + j] * att[e]
// D = 64 floats = 16 float4-lanes per edge.
// Block of 256 threads processes 64 edges (1024 lane-tasks, 4 per thread)
// with indices/att staged in shared memory and gathers batched for MLP=4.

static constexpr int D = 64;
static constexpr int EPB = 64;          // edges per block
static constexpr int TASKS = 4;         // lane-tasks per thread (EPB*16/256)

__global__ __launch_bounds__(256)
void scatter_mul_sum_kernel(const float* __restrict__ src_emb,
                            const float* __restrict__ e_att,
                            const int* __restrict__ src_idx,
                            const int* __restrict__ dst_idx,
                            float* __restrict__ out,
                            int num_edges)
{
    __shared__ int   s_src[EPB];
    __shared__ int   s_dst[EPB];
    __shared__ float s_att[EPB];

    const int t = threadIdx.x;
    const int base = blockIdx.x * EPB;

    // Stage edge metadata once per block.
    if (t < EPB) {
        const int e = base + t;
        const bool valid = e < num_edges;
        s_src[t] = valid ? src_idx[e] : 0;
        s_dst[t] = valid ? dst_idx[e] : 0;
        s_att[t] = valid ? e_att[e]   : 0.0f;
    }
    __syncthreads();

    // Decode the 4 tasks for this thread.
    int   le[TASKS], lane[TASKS];
    bool  ok[TASKS];
    const float* gptr[TASKS];
    float* dptr[TASKS];
    float att[TASKS];

#pragma unroll
    for (int k = 0; k < TASKS; k++) {
        const int task = t + k * 256;
        le[k]   = task >> 4;
        lane[k] = task & 15;
        ok[k]   = (base + le[k]) < num_edges;
        const long long s = s_src[le[k]];
        const long long d = s_dst[le[k]];
        att[k]  = s_att[le[k]];
        gptr[k] = src_emb + s * D + lane[k] * 4;
        dptr[k] = out     + d * D + lane[k] * 4;
    }

    // Batched gathers: 4 independent LDG.128 in flight (MLP=4).
    float4 v[TASKS];
#pragma unroll
    for (int k = 0; k < TASKS; k++) {
        v[k] = ok[k] ? __ldcg(reinterpret_cast<const float4*>(gptr[k]))
                     : make_float4(0.f, 0.f, 0.f, 0.f);
    }

#pragma unroll
    for (int k = 0; k < TASKS; k++) {
        if (!ok[k]) continue;
        const float a = att[k];
        const float x = v[k].x * a;
        const float y = v[k].y * a;
        const float z = v[k].z * a;
        const float w = v[k].w * a;
        asm volatile("red.global.add.v4.f32 [%0], {%1, %2, %3, %4};"
                     :: "l"(dptr[k]), "f"(x), "f"(y), "f"(z), "f"(w)
                     : "memory");
    }
}

extern "C" void kernel_launch(void* const* d_in, const int* in_sizes, int n_in,
                              void* d_out, int out_size)
{
    const float* src_emb = (const float*)d_in[0];   // [N_SRC, 64]
    const float* e_att   = (const float*)d_in[1];   // [E, 1]
    const int*   src_idx = (const int*)d_in[2];     // [E] int32
    const int*   dst_idx = (const int*)d_in[3];     // [E] int32
    float* out = (float*)d_out;                     // [N_DST, 64]

    const int E = in_sizes[2];

    cudaMemsetAsync(d_out, 0, (size_t)out_size * sizeof(float), 0);

    const int grid = (E + EPB - 1) / EPB;
    scatter_mul_sum_kernel<<<grid, 256>>>(src_emb, e_att, src_idx, dst_idx, out, E);
}